// round 4
// baseline (speedup 1.0000x reference)
#include <cuda_runtime.h>
#include <mma.h>
#include <cstdint>

using namespace nvcuda;

// Problem constants (fixed shapes)
#define DMODEL 1024
#define SEQ    2048
#define NB     4
#define MT     (NB * SEQ)   // 8192 total rows

// ---------------- scratch (device globals; no allocation allowed) -----------
__device__ float g_Q[(size_t)MT * DMODEL];          // 32 MB (tf32-rounded)
__device__ float g_K[(size_t)MT * DMODEL];          // 32 MB (tf32-rounded)
__device__ float g_V[(size_t)MT * DMODEL];          // 32 MB (tf32-rounded)
__device__ float g_S[(size_t)NB * SEQ * SEQ];       // 64 MB scores/attn
__device__ float g_W[(size_t)MT * DMODEL];          // 32 MB attn@V (tf32-rounded)
__device__ float g_P[(size_t)MT * DMODEL];          // 32 MB out proj
__device__ float g_RQ[(size_t)MT * DMODEL];         // 32 MB rounded inputQ
__device__ float g_RK[(size_t)MT * DMODEL];         // 32 MB rounded inputK
__device__ float g_RV[(size_t)MT * DMODEL];         // 32 MB rounded inputV
__device__ float g_rW[4][(size_t)DMODEL * DMODEL];  // 16 MB rounded WQ,WK,WV,WO

// ---------------- tf32 rounding (once per element) ---------------------------
__device__ __forceinline__ float to_tf32(float x) {
    float y;
    asm("cvt.rna.tf32.f32 %0, %1;\n" : "=f"(y) : "f"(x));
    return y;
}

__global__ __launch_bounds__(256) void round_tf32(
    const float* __restrict__ x, float* __restrict__ y, int n4)
{
    int i = blockIdx.x * 256 + threadIdx.x;
    if (i < n4) {
        float4 v = ((const float4*)x)[i];
        v.x = to_tf32(v.x); v.y = to_tf32(v.y);
        v.z = to_tf32(v.z); v.w = to_tf32(v.w);
        ((float4*)y)[i] = v;
    }
}

// ---------------- tf32 WMMA GEMM, cp.async 3-stage, 2 CTAs/SM ----------------
// C[M,N] = A[M,K] * op(B)   per batch (blockIdx.z). Operands MUST already be
// tf32-rounded. 128x128 CTA tile, 64x32 warp tiles, 8 warps, <=128 regs so two
// CTAs co-reside per SM (4 warps/SMSP for latency hiding across barriers).
// BT=true : B is [N,K] row-major (C = A * B^T).  BT=false: B is [K,N].
// RC=true : round C to tf32 on store (it feeds a later GEMM).
constexpr int BM = 128, BN = 128, BK = 32;
constexpr int KP = 36;    // padded smem K stride (floats)
constexpr int NP = 132;   // padded smem N stride (floats) for NN B tile
constexpr int STAGES = 3;

__device__ __forceinline__ void cp16(uint32_t saddr, const void* gptr) {
    asm volatile("cp.async.cg.shared.global [%0], [%1], 16;\n"
                 :: "r"(saddr), "l"(gptr) : "memory");
}
__device__ __forceinline__ void cp_commit() {
    asm volatile("cp.async.commit_group;\n" ::: "memory");
}
__device__ __forceinline__ void cp_wait1() {
    asm volatile("cp.async.wait_group 1;\n" ::: "memory");
}

template <bool BT, bool RC>
__global__ __launch_bounds__(256, 2) void gemm_tf32(
    const float* __restrict__ A, const float* __restrict__ Bm,
    float* __restrict__ C, int M, int N, int K,
    long long sA, long long sB, long long sC)
{
    A  += (long long)blockIdx.z * sA;
    Bm += (long long)blockIdx.z * sB;
    C  += (long long)blockIdx.z * sC;

    extern __shared__ float smem[];
    constexpr int ASZ = BM * KP;                       // floats per A stage
    constexpr int BSZ = BT ? (BN * KP) : (BK * NP);    // floats per B stage
    float* As = smem;
    float* Bs = smem + STAGES * ASZ;

    const int t    = threadIdx.x;
    const int warp = t >> 5;
    const int wm   = (warp >> 2) * 64;   // 2 warps along M
    const int wn   = (warp & 3) * 32;    // 4 warps along N
    const int bm   = blockIdx.y * BM;
    const int bn   = blockIdx.x * BN;

    const uint32_t as_base = (uint32_t)__cvta_generic_to_shared(As);
    const uint32_t bs_base = (uint32_t)__cvta_generic_to_shared(Bs);

    auto load_stage = [&](int st, int kt0) {
        uint32_t ab = as_base + (uint32_t)(st * ASZ) * 4u;
        uint32_t bb = bs_base + (uint32_t)(st * BSZ) * 4u;
        // A tile: 128 x 32 -> 1024 float4, 4 per thread
#pragma unroll
        for (int i = 0; i < 4; i++) {
            int idx = t + i * 256;
            int r = idx >> 3, c4 = (idx & 7) << 2;
            cp16(ab + (uint32_t)(r * KP + c4) * 4u,
                 &A[(long long)(bm + r) * K + kt0 + c4]);
        }
        if constexpr (BT) {
            // B tile: 128 n x 32 k
#pragma unroll
            for (int i = 0; i < 4; i++) {
                int idx = t + i * 256;
                int r = idx >> 3, c4 = (idx & 7) << 2;
                cp16(bb + (uint32_t)(r * KP + c4) * 4u,
                     &Bm[(long long)(bn + r) * K + kt0 + c4]);
            }
        } else {
            // B tile: 32 k x 128 n
#pragma unroll
            for (int i = 0; i < 4; i++) {
                int idx = t + i * 256;
                int r = idx >> 5, c4 = (idx & 31) << 2;
                cp16(bb + (uint32_t)(r * NP + c4) * 4u,
                     &Bm[(long long)(kt0 + r) * N + bn + c4]);
            }
        }
    };

    wmma::fragment<wmma::accumulator, 16, 16, 8, float> cf[4][2];
#pragma unroll
    for (int i = 0; i < 4; i++)
#pragma unroll
        for (int j = 0; j < 2; j++) wmma::fill_fragment(cf[i][j], 0.0f);

    const int KT = K / BK;

    // prologue: fill STAGES-1 stages
#pragma unroll
    for (int s = 0; s < STAGES - 1; s++) {
        load_stage(s, s * BK);
        cp_commit();
    }

    for (int kt = 0; kt < KT; kt++) {
        cp_wait1();            // stage kt resident
        __syncthreads();       // all warps finished compute(kt-1)

        int f = kt + STAGES - 1;
        if (f < KT) load_stage(f % STAGES, f * BK);
        cp_commit();

        const float* Asw = As + (kt % STAGES) * ASZ;
        const float* Bsw = Bs + (kt % STAGES) * BSZ;

#pragma unroll
        for (int ks = 0; ks < BK; ks += 8) {
            wmma::fragment<wmma::matrix_a, 16, 16, 8, wmma::precision::tf32,
                           wmma::row_major> af[4];
#pragma unroll
            for (int i = 0; i < 4; i++)
                wmma::load_matrix_sync(af[i], &Asw[(wm + i * 16) * KP + ks], KP);

            if constexpr (BT) {
                wmma::fragment<wmma::matrix_b, 16, 16, 8, wmma::precision::tf32,
                               wmma::col_major> bf[2];
#pragma unroll
                for (int j = 0; j < 2; j++)
                    wmma::load_matrix_sync(bf[j], &Bsw[(wn + j * 16) * KP + ks], KP);
#pragma unroll
                for (int i = 0; i < 4; i++)
#pragma unroll
                    for (int j = 0; j < 2; j++)
                        wmma::mma_sync(cf[i][j], af[i], bf[j], cf[i][j]);
            } else {
                wmma::fragment<wmma::matrix_b, 16, 16, 8, wmma::precision::tf32,
                               wmma::row_major> bf[2];
#pragma unroll
                for (int j = 0; j < 2; j++)
                    wmma::load_matrix_sync(bf[j], &Bsw[ks * NP + wn + j * 16], NP);
#pragma unroll
                for (int i = 0; i < 4; i++)
#pragma unroll
                    for (int j = 0; j < 2; j++)
                        wmma::mma_sync(cf[i][j], af[i], bf[j], cf[i][j]);
            }
        }
    }

#pragma unroll
    for (int i = 0; i < 4; i++)
#pragma unroll
        for (int j = 0; j < 2; j++) {
            if constexpr (RC) {
#pragma unroll
                for (int e = 0; e < cf[i][j].num_elements; e++)
                    cf[i][j].x[e] = to_tf32(cf[i][j].x[e]);
            }
            wmma::store_matrix_sync(
                &C[(long long)(bm + wm + i * 16) * N + bn + wn + j * 16],
                cf[i][j], N, wmma::mem_row_major);
        }
}

// ---------------- masked scaled softmax (tf32-rounded output) ----------------
__global__ __launch_bounds__(256) void softmax_mask(
    float* __restrict__ S, const int* __restrict__ mask)
{
    const long long row = blockIdx.x;
    float* sr = S + row * (long long)SEQ;
    const int* mr = mask + row * (long long)SEQ;
    const int t = threadIdx.x;

    float v[8];
    float mx = -3.0e38f;
#pragma unroll
    for (int i = 0; i < 8; i++) {
        int c = t + i * 256;
        float s = sr[c] * 0.125f;
        if (mr[c] == 1) s = -1e9f;
        v[i] = s;
        mx = fmaxf(mx, s);
    }

    __shared__ float red[8];
#pragma unroll
    for (int o = 16; o; o >>= 1) mx = fmaxf(mx, __shfl_xor_sync(~0u, mx, o));
    if ((t & 31) == 0) red[t >> 5] = mx;
    __syncthreads();
    mx = red[0];
#pragma unroll
    for (int i = 1; i < 8; i++) mx = fmaxf(mx, red[i]);

    float sum = 0.f;
#pragma unroll
    for (int i = 0; i < 8; i++) {
        v[i] = exp2f((v[i] - mx) * 1.4426950408889634f);
        sum += v[i];
    }
#pragma unroll
    for (int o = 16; o; o >>= 1) sum += __shfl_xor_sync(~0u, sum, o);
    __syncthreads();
    if ((t & 31) == 0) red[t >> 5] = sum;
    __syncthreads();
    sum = 0.f;
#pragma unroll
    for (int i = 0; i < 8; i++) sum += red[i];
    float inv = 1.0f / sum;
#pragma unroll
    for (int i = 0; i < 8; i++) sr[t + i * 256] = to_tf32(v[i] * inv);
}

// ---------------- residual add + LayerNorm -----------------------------------
__global__ __launch_bounds__(256) void add_layernorm(
    const float* __restrict__ P, const float* __restrict__ R,
    const float* __restrict__ gamma, const float* __restrict__ beta,
    float* __restrict__ O)
{
    const long long row = blockIdx.x;
    const float* pr = P + row * (long long)DMODEL;
    const float* rr = R + row * (long long)DMODEL;
    float* orow = O + row * (long long)DMODEL;
    const int t = threadIdx.x;

    float x[4];
    float s = 0.f;
#pragma unroll
    for (int i = 0; i < 4; i++) {
        int c = t + i * 256;
        x[i] = pr[c] + rr[c];
        s += x[i];
    }

    __shared__ float red[8];
#pragma unroll
    for (int o = 16; o; o >>= 1) s += __shfl_xor_sync(~0u, s, o);
    if ((t & 31) == 0) red[t >> 5] = s;
    __syncthreads();
    s = 0.f;
#pragma unroll
    for (int i = 0; i < 8; i++) s += red[i];
    const float mu = s * (1.0f / DMODEL);

    float vq = 0.f;
#pragma unroll
    for (int i = 0; i < 4; i++) {
        float d = x[i] - mu;
        vq += d * d;
    }
#pragma unroll
    for (int o = 16; o; o >>= 1) vq += __shfl_xor_sync(~0u, vq, o);
    __syncthreads();
    if ((t & 31) == 0) red[t >> 5] = vq;
    __syncthreads();
    vq = 0.f;
#pragma unroll
    for (int i = 0; i < 8; i++) vq += red[i];
    const float rs = rsqrtf(vq * (1.0f / DMODEL) + 1e-5f);

#pragma unroll
    for (int i = 0; i < 4; i++) {
        int c = t + i * 256;
        orow[c] = (x[i] - mu) * rs * gamma[c] + beta[c];
    }
}

// ---------------- launch ------------------------------------------------------
extern "C" void kernel_launch(void* const* d_in, const int* in_sizes, int n_in,
                              void* d_out, int out_size)
{
    (void)in_sizes; (void)n_in; (void)out_size;
    const float* inQ  = (const float*)d_in[0];
    const float* inK  = (const float*)d_in[1];
    const float* inV  = (const float*)d_in[2];
    const int*   mask = (const int*)  d_in[3];
    const float* WQ   = (const float*)d_in[4];
    const float* WK   = (const float*)d_in[5];
    const float* WV   = (const float*)d_in[6];
    const float* WO   = (const float*)d_in[7];
    const float* gam  = (const float*)d_in[8];
    const float* bet  = (const float*)d_in[9];
    float* out = (float*)d_out;

    float *Q, *K, *V, *S, *W, *P, *RQ, *RK, *RV, *rW;
    cudaGetSymbolAddress((void**)&Q,  g_Q);
    cudaGetSymbolAddress((void**)&K,  g_K);
    cudaGetSymbolAddress((void**)&V,  g_V);
    cudaGetSymbolAddress((void**)&S,  g_S);
    cudaGetSymbolAddress((void**)&W,  g_W);
    cudaGetSymbolAddress((void**)&P,  g_P);
    cudaGetSymbolAddress((void**)&RQ, g_RQ);
    cudaGetSymbolAddress((void**)&RK, g_RK);
    cudaGetSymbolAddress((void**)&RV, g_RV);
    cudaGetSymbolAddress((void**)&rW, g_rW);
    float* rWQ = rW;
    float* rWK = rW + (size_t)DMODEL * DMODEL;
    float* rWV = rW + 2 * (size_t)DMODEL * DMODEL;
    float* rWO = rW + 3 * (size_t)DMODEL * DMODEL;

    constexpr int SMEM_T = STAGES * (BM * KP + BN * KP) * (int)sizeof(float);
    constexpr int SMEM_N = STAGES * (BM * KP + BK * NP) * (int)sizeof(float);
    cudaFuncSetAttribute(gemm_tf32<true, true>,
                         cudaFuncAttributeMaxDynamicSharedMemorySize, SMEM_T);
    cudaFuncSetAttribute(gemm_tf32<true, false>,
                         cudaFuncAttributeMaxDynamicSharedMemorySize, SMEM_T);
    cudaFuncSetAttribute(gemm_tf32<false, true>,
                         cudaFuncAttributeMaxDynamicSharedMemorySize, SMEM_N);

    const dim3 blk(256);
    const long long sQK = (long long)SEQ * DMODEL;
    const long long sSS = (long long)SEQ * SEQ;

    // Pre-round inputs and weights to tf32 (once per element)
    const int nBig4 = MT * DMODEL / 4;
    const int nW4   = DMODEL * DMODEL / 4;
    round_tf32<<<(nBig4 + 255) / 256, 256>>>(inQ, RQ, nBig4);
    round_tf32<<<(nBig4 + 255) / 256, 256>>>(inK, RK, nBig4);
    round_tf32<<<(nBig4 + 255) / 256, 256>>>(inV, RV, nBig4);
    round_tf32<<<(nW4 + 255) / 256, 256>>>(WQ, rWQ, nW4);
    round_tf32<<<(nW4 + 255) / 256, 256>>>(WK, rWK, nW4);
    round_tf32<<<(nW4 + 255) / 256, 256>>>(WV, rWV, nW4);
    round_tf32<<<(nW4 + 255) / 256, 256>>>(WO, rWO, nW4);

    // Projections: [8192,1024] = X * W^T   (outputs rounded: feed later GEMMs)
    gemm_tf32<true, true><<<dim3(DMODEL / BN, MT / BM, 1), blk, SMEM_T>>>(
        RQ, rWQ, Q, MT, DMODEL, DMODEL, 0, 0, 0);
    gemm_tf32<true, true><<<dim3(DMODEL / BN, MT / BM, 1), blk, SMEM_T>>>(
        RK, rWK, K, MT, DMODEL, DMODEL, 0, 0, 0);
    gemm_tf32<true, true><<<dim3(DMODEL / BN, MT / BM, 1), blk, SMEM_T>>>(
        RV, rWV, V, MT, DMODEL, DMODEL, 0, 0, 0);

    // Scores: per batch [2048,2048] = Q * K^T  (raw fp32 out; softmax rounds)
    gemm_tf32<true, false><<<dim3(SEQ / BN, SEQ / BM, NB), blk, SMEM_T>>>(
        Q, K, S, SEQ, SEQ, DMODEL, sQK, sQK, sSS);

    // mask + scale + softmax (in place, tf32-rounded output)
    softmax_mask<<<NB * SEQ, 256>>>(S, mask);

    // attn @ V: per batch [2048,1024] = A * V  (rounded: feeds out proj)
    gemm_tf32<false, true><<<dim3(DMODEL / BN, SEQ / BM, NB), blk, SMEM_N>>>(
        S, V, W, SEQ, DMODEL, SEQ, sSS, sQK, sQK);

    // out proj: [8192,1024] = W * WO^T  (full fp32 out)
    gemm_tf32<true, false><<<dim3(DMODEL / BN, MT / BM, 1), blk, SMEM_T>>>(
        W, rWO, P, MT, DMODEL, DMODEL, 0, 0, 0);

    // residual + layernorm -> d_out
    add_layernorm<<<MT, 256>>>(P, inQ, gam, bet, out);
}

// round 6
// speedup vs baseline: 3.3002x; 3.3002x over previous
#include <cuda_runtime.h>
#include <cuda_fp16.h>
#include <mma.h>
#include <cstdint>

using namespace nvcuda;

// Problem constants (fixed shapes)
#define DMODEL 1024
#define SEQ    2048
#define NB     4
#define MT     (NB * SEQ)   // 8192 total rows

// ---------------- scratch (device globals; no allocation allowed) -----------
// fp16 buffers kept as ushort arrays (trivially-initializable device globals)
__device__ unsigned short g_hRQ[(size_t)MT * DMODEL];        // 16 MB inputQ (half)
__device__ unsigned short g_hRK[(size_t)MT * DMODEL];        // 16 MB inputK (half)
__device__ unsigned short g_hRV[(size_t)MT * DMODEL];        // 16 MB inputV (half)
__device__ unsigned short g_hW4[4][(size_t)DMODEL * DMODEL]; // 8 MB  WQ,WK,WV,WO (half)
__device__ unsigned short g_hQ[(size_t)MT * DMODEL];         // 16 MB proj Q (half)
__device__ unsigned short g_hK[(size_t)MT * DMODEL];         // 16 MB proj K (half)
__device__ unsigned short g_hV[(size_t)MT * DMODEL];         // 16 MB proj V (half)
__device__ unsigned short g_hA[(size_t)NB * SEQ * SEQ];      // 32 MB attn (half)
__device__ unsigned short g_hWv[(size_t)MT * DMODEL];        // 16 MB attn@V (half)
__device__ float g_S[(size_t)NB * SEQ * SEQ];                // 64 MB scores (fp32)
__device__ float g_P[(size_t)MT * DMODEL];                   // 32 MB out proj (fp32)

// ---------------- fp16 WMMA GEMM, cp.async 4-stage ---------------------------
// C[M,N] = A[M,K] * op(B); A,[B] are __half row-major. BT=true: B is [N,K]
// (C = A*B^T); BT=false: B is [K,N]. HC=true: C stored as half (via smem
// staging); HC=false: C stored fp32 directly.
// CTA tile 128x256, BK=32, 8 warps with 64x64 warp tiles, fp32 accumulate.
constexpr int BM = 128, BN = 256, BK = 32;
constexpr int KP = 40;    // padded smem K stride (halves); 80 B rows
constexpr int NP = 264;   // padded smem N stride (halves) for NN B tile; 528 B
constexpr int STG = 4;
constexpr int ASZ   = BM * KP;    // halves per A stage (5120)
constexpr int BSZ_T = BN * KP;    // halves per NT B stage (10240)
constexpr int BSZ_N = BK * NP;    // halves per NN B stage (8448)
constexpr int GSMEM = 131072;     // >= pipeline (122880) and staging (131072)

__device__ __forceinline__ void cp16(uint32_t saddr, const void* gptr) {
    asm volatile("cp.async.cg.shared.global [%0], [%1], 16;\n"
                 :: "r"(saddr), "l"(gptr) : "memory");
}
__device__ __forceinline__ void cp_commit() {
    asm volatile("cp.async.commit_group;\n" ::: "memory");
}

template <bool BT, bool HC>
__global__ __launch_bounds__(256, 1) void gemm_h(
    const __half* __restrict__ A, const __half* __restrict__ Bm,
    void* __restrict__ Cv, int N, int K,
    long long sA, long long sB, long long sC)
{
    A  += (long long)blockIdx.z * sA;
    Bm += (long long)blockIdx.z * sB;

    extern __shared__ __half sm[];
    constexpr int BSZ = BT ? BSZ_T : BSZ_N;
    __half* As = sm;
    __half* Bs = sm + STG * ASZ;

    const int t    = threadIdx.x;
    const int w    = t >> 5;
    const int lid  = t & 31;
    const int wm   = (w >> 2) * 64;   // 2 warps along M
    const int wn   = (w & 3) * 64;    // 4 warps along N
    const int bm   = blockIdx.y * BM;
    const int bn   = blockIdx.x * BN;

    const uint32_t as_base = (uint32_t)__cvta_generic_to_shared(As);
    const uint32_t bs_base = (uint32_t)__cvta_generic_to_shared(Bs);

    auto load_stage = [&](int s, int k0) {
        uint32_t ab = as_base + (uint32_t)(s * ASZ) * 2u;
        uint32_t bb = bs_base + (uint32_t)(s * BSZ) * 2u;
        // A tile: 128 rows x 32 halves -> 512 x cp16 (2 per thread)
#pragma unroll
        for (int i = 0; i < 2; i++) {
            int idx = t + i * 256;
            int r = idx >> 2, c8 = (idx & 3) << 3;
            cp16(ab + (uint32_t)(r * KP + c8) * 2u,
                 &A[(long long)(bm + r) * K + k0 + c8]);
        }
        if constexpr (BT) {
            // B tile: 256 n-rows x 32 halves -> 1024 x cp16 (4 per thread)
#pragma unroll
            for (int i = 0; i < 4; i++) {
                int idx = t + i * 256;
                int r = idx >> 2, c8 = (idx & 3) << 3;
                cp16(bb + (uint32_t)(r * KP + c8) * 2u,
                     &Bm[(long long)(bn + r) * K + k0 + c8]);
            }
        } else {
            // B tile: 32 k-rows x 256 halves -> 1024 x cp16
#pragma unroll
            for (int i = 0; i < 4; i++) {
                int idx = t + i * 256;
                int r = idx >> 5, c8 = (idx & 31) << 3;
                cp16(bb + (uint32_t)(r * NP + c8) * 2u,
                     &Bm[(long long)(k0 + r) * N + bn + c8]);
            }
        }
    };

    wmma::fragment<wmma::accumulator, 16, 16, 16, float> cf[4][4];
#pragma unroll
    for (int i = 0; i < 4; i++)
#pragma unroll
        for (int j = 0; j < 4; j++) wmma::fill_fragment(cf[i][j], 0.0f);

    const int KT = K / BK;

#pragma unroll
    for (int s = 0; s < STG - 1; s++) { load_stage(s, s * BK); cp_commit(); }

    for (int kt = 0; kt < KT; kt++) {
        asm volatile("cp.async.wait_group 2;\n" ::: "memory");
        __syncthreads();

        int f = kt + STG - 1;
        if (f < KT) load_stage(f & (STG - 1), f * BK);
        cp_commit();

        const __half* Asw = As + (kt & (STG - 1)) * ASZ;
        const __half* Bsw = Bs + (kt & (STG - 1)) * BSZ;

#pragma unroll
        for (int ks = 0; ks < BK; ks += 16) {
            wmma::fragment<wmma::matrix_a, 16, 16, 16, __half, wmma::row_major> af[4];
#pragma unroll
            for (int i = 0; i < 4; i++)
                wmma::load_matrix_sync(af[i], &Asw[(wm + i * 16) * KP + ks], KP);

            if constexpr (BT) {
                wmma::fragment<wmma::matrix_b, 16, 16, 16, __half, wmma::col_major> bf[4];
#pragma unroll
                for (int j = 0; j < 4; j++)
                    wmma::load_matrix_sync(bf[j], &Bsw[(wn + j * 16) * KP + ks], KP);
#pragma unroll
                for (int i = 0; i < 4; i++)
#pragma unroll
                    for (int j = 0; j < 4; j++)
                        wmma::mma_sync(cf[i][j], af[i], bf[j], cf[i][j]);
            } else {
                wmma::fragment<wmma::matrix_b, 16, 16, 16, __half, wmma::row_major> bf[4];
#pragma unroll
                for (int j = 0; j < 4; j++)
                    wmma::load_matrix_sync(bf[j], &Bsw[ks * NP + wn + j * 16], NP);
#pragma unroll
                for (int i = 0; i < 4; i++)
#pragma unroll
                    for (int j = 0; j < 4; j++)
                        wmma::mma_sync(cf[i][j], af[i], bf[j], cf[i][j]);
            }
        }
    }

    if constexpr (HC) {
        // stage fp32 accumulators in smem, emit coalesced fp16 stores
        __syncthreads();   // all MMA smem reads done; safe to reuse buffers
        float* stg = (float*)sm + (size_t)w * 4096;   // 64x64 per warp
#pragma unroll
        for (int i = 0; i < 4; i++)
#pragma unroll
            for (int j = 0; j < 4; j++)
                wmma::store_matrix_sync(&stg[(i * 16) * 64 + j * 16], cf[i][j],
                                        64, wmma::mem_row_major);
        __syncwarp();
        __half* Ch = (__half*)Cv + (long long)blockIdx.z * sC;
#pragma unroll
        for (int k = 0; k < 16; k++) {
            int idx = lid + k * 32;          // 512 chunks of 8 halves
            int r = idx >> 3, cc = (idx & 7) << 3;
            const float* src = &stg[r * 64 + cc];
            __half2 h0 = __floats2half2_rn(src[0], src[1]);
            __half2 h1 = __floats2half2_rn(src[2], src[3]);
            __half2 h2 = __floats2half2_rn(src[4], src[5]);
            __half2 h3 = __floats2half2_rn(src[6], src[7]);
            uint4 u;
            u.x = *(uint32_t*)&h0; u.y = *(uint32_t*)&h1;
            u.z = *(uint32_t*)&h2; u.w = *(uint32_t*)&h3;
            *(uint4*)&Ch[(long long)(bm + wm + r) * N + bn + wn + cc] = u;
        }
    } else {
        float* Cf = (float*)Cv + (long long)blockIdx.z * sC;
#pragma unroll
        for (int i = 0; i < 4; i++)
#pragma unroll
            for (int j = 0; j < 4; j++)
                wmma::store_matrix_sync(
                    &Cf[(long long)(bm + wm + i * 16) * N + bn + wn + j * 16],
                    cf[i][j], N, wmma::mem_row_major);
    }
}

// ---------------- fp32 -> fp16 convert (once per element) --------------------
__global__ __launch_bounds__(256) void f2h(
    const float* __restrict__ x, __half* __restrict__ y, int n4)
{
    int i = blockIdx.x * 256 + threadIdx.x;
    if (i < n4) {
        float4 v = ((const float4*)x)[i];
        __half2 a = __floats2half2_rn(v.x, v.y);
        __half2 b = __floats2half2_rn(v.z, v.w);
        uint2 u; u.x = *(uint32_t*)&a; u.y = *(uint32_t*)&b;
        ((uint2*)y)[i] = u;
    }
}

// ---------------- masked scaled softmax: fp32 scores -> fp16 attn ------------
__global__ __launch_bounds__(256) void softmax_mask(
    const float* __restrict__ S, const int* __restrict__ mask,
    __half* __restrict__ Ao)
{
    const long long row = blockIdx.x;
    const float* sr = S + row * (long long)SEQ;
    const int* mr = mask + row * (long long)SEQ;
    __half* ar = Ao + row * (long long)SEQ;
    const int t = threadIdx.x;

    float v[8];
    float mx = -3.0e38f;
#pragma unroll
    for (int i = 0; i < 8; i++) {
        int c = t + i * 256;
        float s = sr[c] * 0.125f;
        if (mr[c] == 1) s = -1e9f;
        v[i] = s;
        mx = fmaxf(mx, s);
    }

    __shared__ float red[8];
#pragma unroll
    for (int o = 16; o; o >>= 1) mx = fmaxf(mx, __shfl_xor_sync(~0u, mx, o));
    if ((t & 31) == 0) red[t >> 5] = mx;
    __syncthreads();
    mx = red[0];
#pragma unroll
    for (int i = 1; i < 8; i++) mx = fmaxf(mx, red[i]);

    float sum = 0.f;
#pragma unroll
    for (int i = 0; i < 8; i++) {
        v[i] = exp2f((v[i] - mx) * 1.4426950408889634f);
        sum += v[i];
    }
#pragma unroll
    for (int o = 16; o; o >>= 1) sum += __shfl_xor_sync(~0u, sum, o);
    __syncthreads();
    if ((t & 31) == 0) red[t >> 5] = sum;
    __syncthreads();
    sum = 0.f;
#pragma unroll
    for (int i = 0; i < 8; i++) sum += red[i];
    float inv = 1.0f / sum;
#pragma unroll
    for (int i = 0; i < 8; i++) ar[t + i * 256] = __float2half_rn(v[i] * inv);
}

// ---------------- residual add + LayerNorm -----------------------------------
__global__ __launch_bounds__(256) void add_layernorm(
    const float* __restrict__ P, const float* __restrict__ R,
    const float* __restrict__ gamma, const float* __restrict__ beta,
    float* __restrict__ O)
{
    const long long row = blockIdx.x;
    const float* pr = P + row * (long long)DMODEL;
    const float* rr = R + row * (long long)DMODEL;
    float* orow = O + row * (long long)DMODEL;
    const int t = threadIdx.x;

    float x[4];
    float s = 0.f;
#pragma unroll
    for (int i = 0; i < 4; i++) {
        int c = t + i * 256;
        x[i] = pr[c] + rr[c];
        s += x[i];
    }

    __shared__ float red[8];
#pragma unroll
    for (int o = 16; o; o >>= 1) s += __shfl_xor_sync(~0u, s, o);
    if ((t & 31) == 0) red[t >> 5] = s;
    __syncthreads();
    s = 0.f;
#pragma unroll
    for (int i = 0; i < 8; i++) s += red[i];
    const float mu = s * (1.0f / DMODEL);

    float vq = 0.f;
#pragma unroll
    for (int i = 0; i < 4; i++) {
        float d = x[i] - mu;
        vq += d * d;
    }
#pragma unroll
    for (int o = 16; o; o >>= 1) vq += __shfl_xor_sync(~0u, vq, o);
    __syncthreads();
    if ((t & 31) == 0) red[t >> 5] = vq;
    __syncthreads();
    vq = 0.f;
#pragma unroll
    for (int i = 0; i < 8; i++) vq += red[i];
    const float rs = rsqrtf(vq * (1.0f / DMODEL) + 1e-5f);

#pragma unroll
    for (int i = 0; i < 4; i++) {
        int c = t + i * 256;
        orow[c] = (x[i] - mu) * rs * gamma[c] + beta[c];
    }
}

// ---------------- launch ------------------------------------------------------
extern "C" void kernel_launch(void* const* d_in, const int* in_sizes, int n_in,
                              void* d_out, int out_size)
{
    (void)in_sizes; (void)n_in; (void)out_size;
    const float* inQ  = (const float*)d_in[0];
    const float* inK  = (const float*)d_in[1];
    const float* inV  = (const float*)d_in[2];
    const int*   mask = (const int*)  d_in[3];
    const float* WQ   = (const float*)d_in[4];
    const float* WK   = (const float*)d_in[5];
    const float* WV   = (const float*)d_in[6];
    const float* WO   = (const float*)d_in[7];
    const float* gam  = (const float*)d_in[8];
    const float* bet  = (const float*)d_in[9];
    float* out = (float*)d_out;

    void *pRQ, *pRK, *pRV, *pW4, *pQ, *pK, *pV, *pA, *pWv, *pS, *pP;
    cudaGetSymbolAddress(&pRQ, g_hRQ);
    cudaGetSymbolAddress(&pRK, g_hRK);
    cudaGetSymbolAddress(&pRV, g_hRV);
    cudaGetSymbolAddress(&pW4, g_hW4);
    cudaGetSymbolAddress(&pQ,  g_hQ);
    cudaGetSymbolAddress(&pK,  g_hK);
    cudaGetSymbolAddress(&pV,  g_hV);
    cudaGetSymbolAddress(&pA,  g_hA);
    cudaGetSymbolAddress(&pWv, g_hWv);
    cudaGetSymbolAddress(&pS,  g_S);
    cudaGetSymbolAddress(&pP,  g_P);
    __half* hRQ = (__half*)pRQ;
    __half* hRK = (__half*)pRK;
    __half* hRV = (__half*)pRV;
    __half* hWQ = (__half*)pW4;
    __half* hWK = hWQ + (size_t)DMODEL * DMODEL;
    __half* hWV = hWQ + 2 * (size_t)DMODEL * DMODEL;
    __half* hWO = hWQ + 3 * (size_t)DMODEL * DMODEL;
    __half* hQ  = (__half*)pQ;
    __half* hK  = (__half*)pK;
    __half* hV  = (__half*)pV;
    __half* hA  = (__half*)pA;
    __half* hWv = (__half*)pWv;
    float*  S   = (float*)pS;
    float*  P   = (float*)pP;

    cudaFuncSetAttribute(gemm_h<true, true>,
                         cudaFuncAttributeMaxDynamicSharedMemorySize, GSMEM);
    cudaFuncSetAttribute(gemm_h<true, false>,
                         cudaFuncAttributeMaxDynamicSharedMemorySize, GSMEM);
    cudaFuncSetAttribute(gemm_h<false, true>,
                         cudaFuncAttributeMaxDynamicSharedMemorySize, GSMEM);

    const dim3 blk(256);
    const long long sQK = (long long)SEQ * DMODEL;
    const long long sSS = (long long)SEQ * SEQ;

    // fp32 -> fp16 conversion (once per element)
    const int nBig4 = MT * DMODEL / 4;
    const int nW4   = DMODEL * DMODEL / 4;
    f2h<<<(nBig4 + 255) / 256, 256>>>(inQ, hRQ, nBig4);
    f2h<<<(nBig4 + 255) / 256, 256>>>(inK, hRK, nBig4);
    f2h<<<(nBig4 + 255) / 256, 256>>>(inV, hRV, nBig4);
    f2h<<<(nW4 + 255) / 256, 256>>>(WQ, hWQ, nW4);
    f2h<<<(nW4 + 255) / 256, 256>>>(WK, hWK, nW4);
    f2h<<<(nW4 + 255) / 256, 256>>>(WV, hWV, nW4);
    f2h<<<(nW4 + 255) / 256, 256>>>(WO, hWO, nW4);

    // Projections: [8192,1024] = X * W^T  -> half
    gemm_h<true, true><<<dim3(DMODEL / BN, MT / BM, 1), blk, GSMEM>>>(
        hRQ, hWQ, hQ, DMODEL, DMODEL, 0, 0, 0);
    gemm_h<true, true><<<dim3(DMODEL / BN, MT / BM, 1), blk, GSMEM>>>(
        hRK, hWK, hK, DMODEL, DMODEL, 0, 0, 0);
    gemm_h<true, true><<<dim3(DMODEL / BN, MT / BM, 1), blk, GSMEM>>>(
        hRV, hWV, hV, DMODEL, DMODEL, 0, 0, 0);

    // Scores: per batch [2048,2048] = Q * K^T -> fp32
    gemm_h<true, false><<<dim3(SEQ / BN, SEQ / BM, NB), blk, GSMEM>>>(
        hQ, hK, S, SEQ, DMODEL, sQK, sQK, sSS);

    // mask + scale + softmax: fp32 scores -> fp16 attn
    softmax_mask<<<NB * SEQ, 256>>>(S, mask, hA);

    // attn @ V: per batch [2048,1024] = A[2048,2048] * V[2048,1024] (NN) -> half
    gemm_h<false, true><<<dim3(DMODEL / BN, SEQ / BM, NB), blk, GSMEM>>>(
        hA, hV, hWv, DMODEL, SEQ, sSS, sQK, sQK);

    // out proj: [8192,1024] = W * WO^T -> fp32
    gemm_h<true, false><<<dim3(DMODEL / BN, MT / BM, 1), blk, GSMEM>>>(
        hWv, hWO, P, DMODEL, DMODEL, 0, 0, 0);

    // residual + layernorm -> d_out
    add_layernorm<<<MT, 256>>>(P, inQ, gam, bet, out);
}

// round 7
// speedup vs baseline: 3.5977x; 1.0902x over previous
#include <cuda_runtime.h>
#include <cuda_fp16.h>
#include <mma.h>
#include <cstdint>

using namespace nvcuda;

// Problem constants (fixed shapes)
#define DMODEL 1024
#define SEQ    2048
#define NB     4
#define MT     (NB * SEQ)   // 8192 total rows

// ---------------- scratch (device globals; no allocation allowed) -----------
__device__ unsigned short g_hRQ[(size_t)MT * DMODEL];        // inputQ (half)
__device__ unsigned short g_hRK[(size_t)MT * DMODEL];        // inputK (half)
__device__ unsigned short g_hRV[(size_t)MT * DMODEL];        // inputV (half)
__device__ unsigned short g_hW4[4][(size_t)DMODEL * DMODEL]; // WQ,WK,WV,WO (half)
__device__ unsigned short g_hQ[(size_t)MT * DMODEL];         // proj Q (half)
__device__ unsigned short g_hK[(size_t)MT * DMODEL];         // proj K (half)
__device__ unsigned short g_hV[(size_t)MT * DMODEL];         // proj V (half)
__device__ unsigned short g_hA[(size_t)NB * SEQ * SEQ];      // attn (half)
__device__ unsigned short g_hWv[(size_t)MT * DMODEL];        // attn@V (half)
__device__ float g_S[(size_t)NB * SEQ * SEQ];                // masked scaled scores
__device__ float g_P[(size_t)MT * DMODEL];                   // out proj (fp32)

// ---------------- fp16 WMMA GEMM, cp.async 4-stage, 2 CTAs/SM ----------------
// C[M,N] = A[M,K] * op(B); A,B are __half row-major.
// BT=true: B is [N,K] (C = A*B^T); BT=false: B is [K,N].
// EPI: 0 = fp32 direct store, 1 = fp16 staged store,
//      2 = masked+scaled fp32 staged store (scores epilogue).
constexpr int BM = 128, BN = 128, BK = 32;
constexpr int KP = 40;    // padded smem K stride (halves); 80 B rows (16B mult)
constexpr int NP = 136;   // padded smem N stride (halves) for NN B tile; 272 B
constexpr int STG = 4;
constexpr int ASZ   = BM * KP;    // 5120 halves per A stage
constexpr int BSZ_T = BN * KP;    // 5120 halves per NT B stage
constexpr int BSZ_N = BK * NP;    // 4352 halves per NN B stage
constexpr int GSMEM = STG * (ASZ + BSZ_T) * 2;   // 81920 B (covers NN + staging)

__device__ __forceinline__ void cp16(uint32_t saddr, const void* gptr) {
    asm volatile("cp.async.cg.shared.global [%0], [%1], 16;\n"
                 :: "r"(saddr), "l"(gptr) : "memory");
}
__device__ __forceinline__ void cp_commit() {
    asm volatile("cp.async.commit_group;\n" ::: "memory");
}

template <bool BT, int EPI>
__global__ __launch_bounds__(256, 2) void gemm_h(
    const __half* __restrict__ A, const __half* __restrict__ Bm,
    void* __restrict__ Cv, const int* __restrict__ mask,
    int N, int K, long long sA, long long sB, long long sC)
{
    A  += (long long)blockIdx.z * sA;
    Bm += (long long)blockIdx.z * sB;

    extern __shared__ __half sm[];
    constexpr int BSZ = BT ? BSZ_T : BSZ_N;
    __half* As = sm;
    __half* Bs = sm + STG * ASZ;

    const int t   = threadIdx.x;
    const int w   = t >> 5;
    const int lid = t & 31;
    const int wm  = (w >> 2) * 64;   // 2 warps along M
    const int wn  = (w & 3) * 32;    // 4 warps along N
    const int bm  = blockIdx.y * BM;
    const int bn  = blockIdx.x * BN;

    const uint32_t as_base = (uint32_t)__cvta_generic_to_shared(As);
    const uint32_t bs_base = (uint32_t)__cvta_generic_to_shared(Bs);

    auto load_stage = [&](int s, int k0) {
        uint32_t ab = as_base + (uint32_t)(s * ASZ) * 2u;
        uint32_t bb = bs_base + (uint32_t)(s * BSZ) * 2u;
        // A tile: 128 rows x 32 halves -> 512 cp16 (2 per thread)
#pragma unroll
        for (int i = 0; i < 2; i++) {
            int idx = t + i * 256;
            int r = idx >> 2, c8 = (idx & 3) << 3;
            cp16(ab + (uint32_t)(r * KP + c8) * 2u,
                 &A[(long long)(bm + r) * K + k0 + c8]);
        }
        if constexpr (BT) {
            // B tile: 128 n-rows x 32 halves
#pragma unroll
            for (int i = 0; i < 2; i++) {
                int idx = t + i * 256;
                int r = idx >> 2, c8 = (idx & 3) << 3;
                cp16(bb + (uint32_t)(r * KP + c8) * 2u,
                     &Bm[(long long)(bn + r) * K + k0 + c8]);
            }
        } else {
            // B tile: 32 k-rows x 128 halves
#pragma unroll
            for (int i = 0; i < 2; i++) {
                int idx = t + i * 256;
                int r = idx >> 4, c8 = (idx & 15) << 3;
                cp16(bb + (uint32_t)(r * NP + c8) * 2u,
                     &Bm[(long long)(k0 + r) * N + bn + c8]);
            }
        }
    };

    wmma::fragment<wmma::accumulator, 16, 16, 16, float> cf[4][2];
#pragma unroll
    for (int i = 0; i < 4; i++)
#pragma unroll
        for (int j = 0; j < 2; j++) wmma::fill_fragment(cf[i][j], 0.0f);

    const int KT = K / BK;

#pragma unroll
    for (int s = 0; s < STG - 1; s++) { load_stage(s, s * BK); cp_commit(); }

    for (int kt = 0; kt < KT; kt++) {
        asm volatile("cp.async.wait_group 2;\n" ::: "memory");
        __syncthreads();

        int f = kt + STG - 1;
        if (f < KT) load_stage(f & (STG - 1), f * BK);
        cp_commit();

        const __half* Asw = As + (kt & (STG - 1)) * ASZ;
        const __half* Bsw = Bs + (kt & (STG - 1)) * BSZ;

#pragma unroll
        for (int ks = 0; ks < BK; ks += 16) {
            wmma::fragment<wmma::matrix_a, 16, 16, 16, __half, wmma::row_major> af[4];
#pragma unroll
            for (int i = 0; i < 4; i++)
                wmma::load_matrix_sync(af[i], &Asw[(wm + i * 16) * KP + ks], KP);

            if constexpr (BT) {
                wmma::fragment<wmma::matrix_b, 16, 16, 16, __half, wmma::col_major> bf[2];
#pragma unroll
                for (int j = 0; j < 2; j++)
                    wmma::load_matrix_sync(bf[j], &Bsw[(wn + j * 16) * KP + ks], KP);
#pragma unroll
                for (int i = 0; i < 4; i++)
#pragma unroll
                    for (int j = 0; j < 2; j++)
                        wmma::mma_sync(cf[i][j], af[i], bf[j], cf[i][j]);
            } else {
                wmma::fragment<wmma::matrix_b, 16, 16, 16, __half, wmma::row_major> bf[2];
#pragma unroll
                for (int j = 0; j < 2; j++)
                    wmma::load_matrix_sync(bf[j], &Bsw[ks * NP + wn + j * 16], NP);
#pragma unroll
                for (int i = 0; i < 4; i++)
#pragma unroll
                    for (int j = 0; j < 2; j++)
                        wmma::mma_sync(cf[i][j], af[i], bf[j], cf[i][j]);
            }
        }
    }

    if constexpr (EPI == 0) {
        float* Cf = (float*)Cv + (long long)blockIdx.z * sC;
#pragma unroll
        for (int i = 0; i < 4; i++)
#pragma unroll
            for (int j = 0; j < 2; j++)
                wmma::store_matrix_sync(
                    &Cf[(long long)(bm + wm + i * 16) * N + bn + wn + j * 16],
                    cf[i][j], N, wmma::mem_row_major);
    } else {
        // stage fp32 accumulators in (reused) smem, 64x32 per warp
        __syncthreads();
        float* stg = (float*)sm + (size_t)w * 2048;
#pragma unroll
        for (int i = 0; i < 4; i++)
#pragma unroll
            for (int j = 0; j < 2; j++)
                wmma::store_matrix_sync(&stg[(i * 16) * 32 + j * 16], cf[i][j],
                                        32, wmma::mem_row_major);
        __syncwarp();
        if constexpr (EPI == 1) {
            __half* Ch = (__half*)Cv + (long long)blockIdx.z * sC;
#pragma unroll
            for (int it = 0; it < 32; it++) {
                int g = it * 32 + lid;            // 1024 half2 chunks
                int r = g >> 4, cp = (g & 15) << 1;
                float2 v = *(const float2*)&stg[r * 32 + cp];
                __half2 h = __floats2half2_rn(v.x, v.y);
                *(__half2*)&Ch[(long long)(bm + wm + r) * N + bn + wn + cp] = h;
            }
        } else {
            // EPI == 2: masked + scaled fp32 store (scores epilogue)
            float* Cf = (float*)Cv + (long long)blockIdx.z * sC;
            const int* Mb = mask + (long long)blockIdx.z * sC;
#pragma unroll
            for (int it = 0; it < 64; it++) {
                int g = it * 32 + lid;            // 2048 floats
                int r = g >> 5, cc = g & 31;
                long long gi = (long long)(bm + wm + r) * N + bn + wn + cc;
                float s = stg[r * 32 + cc] * 0.125f;
                if (Mb[gi] == 1) s = -1e9f;
                Cf[gi] = s;
            }
        }
    }
}

// ---------------- fused fp32 -> fp16 converts ---------------------------------
__global__ __launch_bounds__(256) void f2h3(
    const float* __restrict__ x0, const float* __restrict__ x1,
    const float* __restrict__ x2,
    __half* __restrict__ y0, __half* __restrict__ y1, __half* __restrict__ y2,
    int n4)
{
    const float* x = (blockIdx.y == 0) ? x0 : (blockIdx.y == 1) ? x1 : x2;
    __half*      y = (blockIdx.y == 0) ? y0 : (blockIdx.y == 1) ? y1 : y2;
    int i = blockIdx.x * 256 + threadIdx.x;
    if (i < n4) {
        float4 v = ((const float4*)x)[i];
        __half2 a = __floats2half2_rn(v.x, v.y);
        __half2 b = __floats2half2_rn(v.z, v.w);
        uint2 u; u.x = *(uint32_t*)&a; u.y = *(uint32_t*)&b;
        ((uint2*)y)[i] = u;
    }
}

__global__ __launch_bounds__(256) void f2h4(
    const float* __restrict__ x0, const float* __restrict__ x1,
    const float* __restrict__ x2, const float* __restrict__ x3,
    __half* __restrict__ y, int n4)   // y: 4 consecutive DMODEL^2 blocks
{
    const float* x = (blockIdx.y == 0) ? x0 : (blockIdx.y == 1) ? x1
                   : (blockIdx.y == 2) ? x2 : x3;
    __half* yo = y + (size_t)blockIdx.y * DMODEL * DMODEL;
    int i = blockIdx.x * 256 + threadIdx.x;
    if (i < n4) {
        float4 v = ((const float4*)x)[i];
        __half2 a = __floats2half2_rn(v.x, v.y);
        __half2 b = __floats2half2_rn(v.z, v.w);
        uint2 u; u.x = *(uint32_t*)&a; u.y = *(uint32_t*)&b;
        ((uint2*)yo)[i] = u;
    }
}

// ---------------- softmax over pre-masked scaled rows -> fp16 -----------------
__global__ __launch_bounds__(256) void softmax_rows(
    const float* __restrict__ S, __half* __restrict__ Ao)
{
    const long long row = blockIdx.x;
    const float* sr = S + row * (long long)SEQ;
    __half* ar = Ao + row * (long long)SEQ;
    const int t = threadIdx.x;

    float v[8];
    float mx = -3.0e38f;
#pragma unroll
    for (int i = 0; i < 8; i++) {
        v[i] = sr[t + i * 256];
        mx = fmaxf(mx, v[i]);
    }

    __shared__ float red[8];
#pragma unroll
    for (int o = 16; o; o >>= 1) mx = fmaxf(mx, __shfl_xor_sync(~0u, mx, o));
    if ((t & 31) == 0) red[t >> 5] = mx;
    __syncthreads();
    mx = red[0];
#pragma unroll
    for (int i = 1; i < 8; i++) mx = fmaxf(mx, red[i]);

    float sum = 0.f;
#pragma unroll
    for (int i = 0; i < 8; i++) {
        v[i] = exp2f((v[i] - mx) * 1.4426950408889634f);
        sum += v[i];
    }
#pragma unroll
    for (int o = 16; o; o >>= 1) sum += __shfl_xor_sync(~0u, sum, o);
    __syncthreads();
    if ((t & 31) == 0) red[t >> 5] = sum;
    __syncthreads();
    sum = 0.f;
#pragma unroll
    for (int i = 0; i < 8; i++) sum += red[i];
    float inv = 1.0f / sum;
#pragma unroll
    for (int i = 0; i < 8; i++) ar[t + i * 256] = __float2half_rn(v[i] * inv);
}

// ---------------- residual add + LayerNorm -----------------------------------
__global__ __launch_bounds__(256) void add_layernorm(
    const float* __restrict__ P, const float* __restrict__ R,
    const float* __restrict__ gamma, const float* __restrict__ beta,
    float* __restrict__ O)
{
    const long long row = blockIdx.x;
    const float* pr = P + row * (long long)DMODEL;
    const float* rr = R + row * (long long)DMODEL;
    float* orow = O + row * (long long)DMODEL;
    const int t = threadIdx.x;

    float x[4];
    float s = 0.f;
#pragma unroll
    for (int i = 0; i < 4; i++) {
        int c = t + i * 256;
        x[i] = pr[c] + rr[c];
        s += x[i];
    }

    __shared__ float red[8];
#pragma unroll
    for (int o = 16; o; o >>= 1) s += __shfl_xor_sync(~0u, s, o);
    if ((t & 31) == 0) red[t >> 5] = s;
    __syncthreads();
    s = 0.f;
#pragma unroll
    for (int i = 0; i < 8; i++) s += red[i];
    const float mu = s * (1.0f / DMODEL);

    float vq = 0.f;
#pragma unroll
    for (int i = 0; i < 4; i++) {
        float d = x[i] - mu;
        vq += d * d;
    }
#pragma unroll
    for (int o = 16; o; o >>= 1) vq += __shfl_xor_sync(~0u, vq, o);
    __syncthreads();
    if ((t & 31) == 0) red[t >> 5] = vq;
    __syncthreads();
    vq = 0.f;
#pragma unroll
    for (int i = 0; i < 8; i++) vq += red[i];
    const float rs = rsqrtf(vq * (1.0f / DMODEL) + 1e-5f);

#pragma unroll
    for (int i = 0; i < 4; i++) {
        int c = t + i * 256;
        orow[c] = (x[i] - mu) * rs * gamma[c] + beta[c];
    }
}

// ---------------- launch ------------------------------------------------------
extern "C" void kernel_launch(void* const* d_in, const int* in_sizes, int n_in,
                              void* d_out, int out_size)
{
    (void)in_sizes; (void)n_in; (void)out_size;
    const float* inQ  = (const float*)d_in[0];
    const float* inK  = (const float*)d_in[1];
    const float* inV  = (const float*)d_in[2];
    const int*   mask = (const int*)  d_in[3];
    const float* WQ   = (const float*)d_in[4];
    const float* WK   = (const float*)d_in[5];
    const float* WV   = (const float*)d_in[6];
    const float* WO   = (const float*)d_in[7];
    const float* gam  = (const float*)d_in[8];
    const float* bet  = (const float*)d_in[9];
    float* out = (float*)d_out;

    void *pRQ, *pRK, *pRV, *pW4, *pQ, *pK, *pV, *pA, *pWv, *pS, *pP;
    cudaGetSymbolAddress(&pRQ, g_hRQ);
    cudaGetSymbolAddress(&pRK, g_hRK);
    cudaGetSymbolAddress(&pRV, g_hRV);
    cudaGetSymbolAddress(&pW4, g_hW4);
    cudaGetSymbolAddress(&pQ,  g_hQ);
    cudaGetSymbolAddress(&pK,  g_hK);
    cudaGetSymbolAddress(&pV,  g_hV);
    cudaGetSymbolAddress(&pA,  g_hA);
    cudaGetSymbolAddress(&pWv, g_hWv);
    cudaGetSymbolAddress(&pS,  g_S);
    cudaGetSymbolAddress(&pP,  g_P);
    __half* hRQ = (__half*)pRQ;
    __half* hRK = (__half*)pRK;
    __half* hRV = (__half*)pRV;
    __half* hWQ = (__half*)pW4;
    __half* hWK = hWQ + (size_t)DMODEL * DMODEL;
    __half* hWV = hWQ + 2 * (size_t)DMODEL * DMODEL;
    __half* hWO = hWQ + 3 * (size_t)DMODEL * DMODEL;
    __half* hQ  = (__half*)pQ;
    __half* hK  = (__half*)pK;
    __half* hV  = (__half*)pV;
    __half* hA  = (__half*)pA;
    __half* hWv = (__half*)pWv;
    float*  S   = (float*)pS;
    float*  P   = (float*)pP;

    cudaFuncSetAttribute(gemm_h<true, 1>,
                         cudaFuncAttributeMaxDynamicSharedMemorySize, GSMEM);
    cudaFuncSetAttribute(gemm_h<true, 0>,
                         cudaFuncAttributeMaxDynamicSharedMemorySize, GSMEM);
    cudaFuncSetAttribute(gemm_h<true, 2>,
                         cudaFuncAttributeMaxDynamicSharedMemorySize, GSMEM);
    cudaFuncSetAttribute(gemm_h<false, 1>,
                         cudaFuncAttributeMaxDynamicSharedMemorySize, GSMEM);

    const dim3 blk(256);
    const long long sQK = (long long)SEQ * DMODEL;
    const long long sSS = (long long)SEQ * SEQ;

    // launch 1-2: fused fp32 -> fp16 converts
    const int nBig4 = MT * DMODEL / 4;
    const int nW4   = DMODEL * DMODEL / 4;
    f2h3<<<dim3((nBig4 + 255) / 256, 3), 256>>>(inQ, inK, inV, hRQ, hRK, hRV, nBig4);
    f2h4<<<dim3((nW4 + 255) / 256, 4), 256>>>(WQ, WK, WV, WO, hWQ, nW4);

    // launches 3-5: projections [8192,1024] = X * W^T -> half
    gemm_h<true, 1><<<dim3(DMODEL / BN, MT / BM, 1), blk, GSMEM>>>(
        hRQ, hWQ, hQ, nullptr, DMODEL, DMODEL, 0, 0, 0);
    gemm_h<true, 1><<<dim3(DMODEL / BN, MT / BM, 1), blk, GSMEM>>>(
        hRK, hWK, hK, nullptr, DMODEL, DMODEL, 0, 0, 0);
    gemm_h<true, 1><<<dim3(DMODEL / BN, MT / BM, 1), blk, GSMEM>>>(
        hRV, hWV, hV, nullptr, DMODEL, DMODEL, 0, 0, 0);

    // launch 6 (ncu target): scores = Q*K^T with fused mask+scale -> fp32
    gemm_h<true, 2><<<dim3(SEQ / BN, SEQ / BM, NB), blk, GSMEM>>>(
        hQ, hK, S, mask, SEQ, DMODEL, sQK, sQK, sSS);

    // softmax over pre-masked rows -> fp16 attn
    softmax_rows<<<NB * SEQ, 256>>>(S, hA);

    // attn @ V: per batch [2048,1024] = A * V (NN) -> half
    gemm_h<false, 1><<<dim3(DMODEL / BN, SEQ / BM, NB), blk, GSMEM>>>(
        hA, hV, hWv, nullptr, DMODEL, SEQ, sSS, sQK, sQK);

    // out proj: [8192,1024] = W * WO^T -> fp32
    gemm_h<true, 0><<<dim3(DMODEL / BN, MT / BM, 1), blk, GSMEM>>>(
        hWv, hWO, P, nullptr, DMODEL, DMODEL, 0, 0, 0);

    // residual + layernorm -> d_out
    add_layernorm<<<MT, 256>>>(P, inQ, gam, bet, out);
}